// round 5
// baseline (speedup 1.0000x reference)
#include <cuda_runtime.h>
#include <cuda_bf16.h>
#include <mma.h>
#include <math.h>
#include <stddef.h>
#include <stdint.h>

using namespace nvcuda;

#define BATCH 512
#define TT    256
#define IIN   64
#define HH    256
#define MTOT  (BATCH * TT)          // 131072 rows for x_proj GEMMs

#define CLUSTER   8
#define NCLUSTER  16                // 16 clusters x 32 batches = 512
#define MB        32                // batches per cluster (M of per-step GEMM)
#define NSL       32                // j-slice per CTA
#define NW        128               // N per CTA = 4 gates x 32 j
#define LDW       272               // padded ld (elements) for A and W tiles
#define LDS_      136               // padded ld for fp32 scratch

// smem layout (bf16 elements unless noted):
//   W  : [2(part)][128][LDW]           = 69,632  bf16 = 139,264 B
//   A  : [2(buf)][2(part)][32][LDW]    = 34,816  bf16 =  69,632 B
//   scr: [32][LDS_] fp32               =  4,352  f32  =  17,408 B
#define W_ELEMS   (2 * NW * LDW)
#define A_ELEMS   (2 * 2 * MB * LDW)
#define SMEM_REC  ((W_ELEMS + A_ELEMS) * 2 + MB * LDS_ * 4)

// ---------------- static device scratch ------------------------------------
__device__ __nv_bfloat16 g_xhi[(size_t)MTOT * IIN];
__device__ __nv_bfloat16 g_xlo[(size_t)MTOT * IIN];
__device__ __nv_bfloat16 g_w0hi[4 * HH * IIN];
__device__ __nv_bfloat16 g_w0lo[4 * HH * IIN];
__device__ __nv_bfloat16 g_w1hi[4 * HH * HH];
__device__ __nv_bfloat16 g_w1lo[4 * HH * HH];
__device__ __nv_bfloat16 g_h1hi[(size_t)MTOT * HH];
__device__ __nv_bfloat16 g_h1lo[(size_t)MTOT * HH];
__device__ float g_xp[(size_t)4 * MTOT * HH];     // [4][MTOT][256] gate-major
__device__ float g_h2last[BATCH * HH];

// ---------------- conversions ------------------------------------------------
__global__ void cvt_pair_kernel(const float* __restrict__ src,
                                __nv_bfloat16* __restrict__ hi,
                                __nv_bfloat16* __restrict__ lo, size_t n)
{
    for (size_t i = (size_t)blockIdx.x * blockDim.x + threadIdx.x; i < n;
         i += (size_t)gridDim.x * blockDim.x) {
        float v = src[i];
        __nv_bfloat16 h = __float2bfloat16(v);
        hi[i] = h;
        lo[i] = __float2bfloat16(v - __bfloat162float(h));
    }
}

// ---------------- x_proj GEMM on HMMA (wmma, bf16 hi/lo 3-term) --------------
template <int K>
__global__ __launch_bounds__(256, 1)
void gemm_xproj_wmma(const __nv_bfloat16* __restrict__ Ahi,
                     const __nv_bfloat16* __restrict__ Alo,
                     const __nv_bfloat16* __restrict__ Bhi,
                     const __nv_bfloat16* __restrict__ Blo,
                     float* __restrict__ xp)
{
    const int w  = threadIdx.x >> 5;
    const int wm = w & 3, wn = w >> 2;
    const size_t m0 = (size_t)blockIdx.x * 128 + wm * 32;
    const int    n0 = blockIdx.y * 128 + wn * 64;

    wmma::fragment<wmma::accumulator, 16, 16, 16, float> acc[2][4];
#pragma unroll
    for (int i = 0; i < 2; ++i)
#pragma unroll
        for (int f = 0; f < 4; ++f) wmma::fill_fragment(acc[i][f], 0.0f);

#pragma unroll
    for (int term = 0; term < 3; ++term) {
        const __nv_bfloat16* A = (term == 1) ? Alo : Ahi;
        const __nv_bfloat16* B = (term == 2) ? Blo : Bhi;
#pragma unroll
        for (int k0 = 0; k0 < K; k0 += 16) {
            wmma::fragment<wmma::matrix_a, 16, 16, 16, __nv_bfloat16,
                           wmma::row_major> fa[2];
            wmma::load_matrix_sync(fa[0], A + m0 * K + k0, K);
            wmma::load_matrix_sync(fa[1], A + (m0 + 16) * K + k0, K);
#pragma unroll
            for (int f = 0; f < 4; ++f) {
                wmma::fragment<wmma::matrix_b, 16, 16, 16, __nv_bfloat16,
                               wmma::col_major> fb;
                wmma::load_matrix_sync(fb, B + (size_t)(n0 + f * 16) * K + k0, K);
                wmma::mma_sync(acc[0][f], fa[0], fb, acc[0][f]);
                wmma::mma_sync(acc[1][f], fa[1], fb, acc[1][f]);
            }
        }
    }

#pragma unroll
    for (int i = 0; i < 2; ++i)
#pragma unroll
        for (int f = 0; f < 4; ++f) {
            int c0 = n0 + f * 16;
            int g = c0 >> 8, j0 = c0 & 255;
            float* dst = xp + ((size_t)g * MTOT + m0 + i * 16) * HH + j0;
            wmma::store_matrix_sync(dst, acc[i][f], HH, wmma::mem_row_major);
        }
}

// ---------------- clustered tensor-core recurrence ---------------------------
// 16 clusters x 8 CTAs. Cluster handles 32 batches; CTA rank r owns
// j in [32r, 32r+32) of ALL 4 gates (N=128 gate-columns), so the c/h state
// update is CTA-local. Per step: [32,256] @ [256,128] bf16 hi/lo 3-term wmma,
// then state update, then h-slice broadcast to all 8 peers via DSMEM, one
// barrier.cluster per step; A (h) is double-buffered.
template <bool STORE_PAIR>
__global__ __launch_bounds__(256, 1) __cluster_dims__(CLUSTER, 1, 1)
void lstm_rec_tc(const float* __restrict__ xp,     // [4][MTOT][256]
                 const float* __restrict__ w_hh,   // [4*256, 256] row-major
                 const float* __restrict__ b_ih,
                 const float* __restrict__ b_hh,
                 __nv_bfloat16* __restrict__ ohi,  // layer0: h1 hi
                 __nv_bfloat16* __restrict__ olo,  // layer0: h1 lo
                 float* __restrict__ olast)        // layer1: [BATCH][HH]
{
    extern __shared__ __align__(16) __nv_bfloat16 smem[];
    __nv_bfloat16* Wsm = smem;                 // [2][128][LDW]
    __nv_bfloat16* Asm = smem + W_ELEMS;       // [2][2][32][LDW]
    float*         scr = (float*)(smem + W_ELEMS + A_ELEMS);  // [32][LDS_]

    const int tid  = threadIdx.x;
    const int wid  = tid >> 5;
    const int rank = blockIdx.x & (CLUSTER - 1);
    const int cl   = blockIdx.x >> 3;
    const int js   = rank * NSL;               // owned j-slice start
    const int b0c  = cl * MB;

    // ---- load W_hh slice -> smem bf16 hi/lo (one-time) ----
    for (int idx = tid; idx < NW * HH; idx += 256) {
        int r = idx >> 8, k = idx & 255;       // r: (g*32 + jj)
        int g = r >> 5, jj = r & 31;
        float v = w_hh[(size_t)(g * HH + js + jj) * HH + k];
        __nv_bfloat16 h = __float2bfloat16(v);
        Wsm[r * LDW + k]            = h;
        Wsm[W_ELEMS / 2 + r * LDW + k] = __float2bfloat16(v - __bfloat162float(h));
    }
    // ---- zero A buffer 0 (h0 = 0), both parts ----
    for (int idx = tid; idx < 2 * MB * LDW; idx += 256)
        Asm[idx] = __float2bfloat16(0.0f);

    // ---- per-thread state-update constants ----
    const int b  = tid >> 3;                   // 0..31 (batch within cluster)
    const int jj = (tid & 7) * 4;              // 4 consecutive j within slice
    float bias[4][4];
#pragma unroll
    for (int g = 0; g < 4; ++g)
#pragma unroll
        for (int v = 0; v < 4; ++v) {
            int r = g * HH + js + jj + v;
            bias[g][v] = b_ih[r] + b_hh[r];
        }
    float c[4] = {0.f, 0.f, 0.f, 0.f};

    __syncthreads();
    asm volatile("barrier.cluster.arrive.aligned;" ::: "memory");
    asm volatile("barrier.cluster.wait.aligned;" ::: "memory");

    const size_t mrow = (size_t)(b0c + b) * TT;   // gmem row base for (b)

    for (int t = 0; t < TT; ++t) {
        const int buf  = t & 1;
        const int nbuf = buf ^ 1;

        // ---- prefetch x_proj gate pre-activations (hide DRAM latency) ----
        float xg[4][4];
#pragma unroll
        for (int g = 0; g < 4; ++g) {
            float4 v = *(const float4*)(xp + ((size_t)g * MTOT + mrow + t) * HH
                                        + js + jj);
            xg[g][0] = v.x; xg[g][1] = v.y; xg[g][2] = v.z; xg[g][3] = v.w;
        }

        // ---- MMA: acc[32,128] = sum over 3 hi/lo terms ----
        {
            wmma::fragment<wmma::accumulator, 16, 16, 16, float> acc0, acc1;
            wmma::fill_fragment(acc0, 0.0f);
            wmma::fill_fragment(acc1, 0.0f);
            const __nv_bfloat16* Ab = Asm + buf * (2 * MB * LDW);
#pragma unroll
            for (int term = 0; term < 3; ++term) {
                const __nv_bfloat16* Ap = Ab + (term == 1 ? MB * LDW : 0);
                const __nv_bfloat16* Wp = Wsm + (term == 2 ? W_ELEMS / 2 : 0);
#pragma unroll
                for (int k0 = 0; k0 < HH; k0 += 16) {
                    wmma::fragment<wmma::matrix_a, 16, 16, 16, __nv_bfloat16,
                                   wmma::row_major> a0, a1;
                    wmma::load_matrix_sync(a0, Ap + k0, LDW);
                    wmma::load_matrix_sync(a1, Ap + 16 * LDW + k0, LDW);
                    wmma::fragment<wmma::matrix_b, 16, 16, 16, __nv_bfloat16,
                                   wmma::col_major> fb;
                    wmma::load_matrix_sync(fb, Wp + wid * 16 * LDW + k0, LDW);
                    wmma::mma_sync(acc0, a0, fb, acc0);
                    wmma::mma_sync(acc1, a1, fb, acc1);
                }
            }
            wmma::store_matrix_sync(scr + wid * 16, acc0, LDS_, wmma::mem_row_major);
            wmma::store_matrix_sync(scr + 16 * LDS_ + wid * 16, acc1, LDS_,
                                    wmma::mem_row_major);
        }
        __syncthreads();

        // ---- state update (thread owns batch b, 4 consecutive j) ----
        float hv[4];
#pragma unroll
        for (int v = 0; v < 4; ++v) {
            float vi = scr[b * LDS_ + 0 * 32 + jj + v] + bias[0][v] + xg[0][v];
            float vf = scr[b * LDS_ + 1 * 32 + jj + v] + bias[1][v] + xg[1][v];
            float vg = scr[b * LDS_ + 2 * 32 + jj + v] + bias[2][v] + xg[2][v];
            float vo = scr[b * LDS_ + 3 * 32 + jj + v] + bias[3][v] + xg[3][v];
            float iv = 1.0f / (1.0f + expf(-vi));
            float fv = 1.0f / (1.0f + expf(-vf));
            float gv = tanhf(vg);
            float ov = 1.0f / (1.0f + expf(-vo));
            c[v] = fv * c[v] + iv * gv;
            hv[v] = ov * tanhf(c[v]);
        }

        // ---- pack hi/lo bf16 ----
        __nv_bfloat162 hiA = __float22bfloat162_rn(make_float2(hv[0], hv[1]));
        __nv_bfloat162 hiB = __float22bfloat162_rn(make_float2(hv[2], hv[3]));
        float l0 = hv[0] - __bfloat162float(__low2bfloat16(hiA));
        float l1 = hv[1] - __bfloat162float(__high2bfloat16(hiA));
        float l2 = hv[2] - __bfloat162float(__low2bfloat16(hiB));
        float l3 = hv[3] - __bfloat162float(__high2bfloat16(hiB));
        __nv_bfloat162 loA = __float22bfloat162_rn(make_float2(l0, l1));
        __nv_bfloat162 loB = __float22bfloat162_rn(make_float2(l2, l3));
        unsigned long long hi64 =
            (unsigned long long)*(uint32_t*)&hiA |
            ((unsigned long long)*(uint32_t*)&hiB << 32);
        unsigned long long lo64 =
            (unsigned long long)*(uint32_t*)&loA |
            ((unsigned long long)*(uint32_t*)&loB << 32);

        // ---- broadcast h-slice to all 8 cluster CTAs (incl. self) ----
        {
            __nv_bfloat16* dhi = Asm + (nbuf * 2 + 0) * MB * LDW + b * LDW + js + jj;
            __nv_bfloat16* dlo = Asm + (nbuf * 2 + 1) * MB * LDW + b * LDW + js + jj;
            uint32_t ahi, alo;
            asm("{ .reg .u64 t; cvta.to.shared.u64 t, %1; cvt.u32.u64 %0, t; }"
                : "=r"(ahi) : "l"(dhi));
            asm("{ .reg .u64 t; cvta.to.shared.u64 t, %1; cvt.u32.u64 %0, t; }"
                : "=r"(alo) : "l"(dlo));
#pragma unroll
            for (int p = 0; p < CLUSTER; ++p) {
                uint32_t rhi, rlo;
                asm("mapa.shared::cluster.u32 %0, %1, %2;"
                    : "=r"(rhi) : "r"(ahi), "r"(p));
                asm("mapa.shared::cluster.u32 %0, %1, %2;"
                    : "=r"(rlo) : "r"(alo), "r"(p));
                asm volatile("st.shared::cluster.u64 [%0], %1;"
                             :: "r"(rhi), "l"(hi64) : "memory");
                asm volatile("st.shared::cluster.u64 [%0], %1;"
                             :: "r"(rlo), "l"(lo64) : "memory");
            }
        }

        // ---- outputs ----
        if (STORE_PAIR) {
            size_t m = mrow + t;
            *(uint2*)&ohi[m * HH + js + jj] =
                make_uint2(*(uint32_t*)&hiA, *(uint32_t*)&hiB);
            *(uint2*)&olo[m * HH + js + jj] =
                make_uint2(*(uint32_t*)&loA, *(uint32_t*)&loB);
        } else if (t == TT - 1) {
            float4 o; o.x = hv[0]; o.y = hv[1]; o.z = hv[2]; o.w = hv[3];
            *(float4*)&olast[(size_t)(b0c + b) * HH + js + jj] = o;
        }

        // ---- cluster barrier: peer writes visible, buffers swap-safe ----
        asm volatile("barrier.cluster.arrive.aligned;" ::: "memory");
        asm volatile("barrier.cluster.wait.aligned;" ::: "memory");
    }
}

// ---------------- LayerNorm + exact GELU + linear head ----------------------
__device__ __forceinline__ float block_sum_256(float v, float* red)
{
    __syncthreads();
#pragma unroll
    for (int o = 16; o > 0; o >>= 1) v += __shfl_down_sync(0xffffffffu, v, o);
    if ((threadIdx.x & 31) == 0) red[threadIdx.x >> 5] = v;
    __syncthreads();
    if (threadIdx.x < 8) {
        v = red[threadIdx.x];
#pragma unroll
        for (int o = 4; o > 0; o >>= 1) v += __shfl_down_sync(0xffu, v, o);
        if (threadIdx.x == 0) red[0] = v;
    }
    __syncthreads();
    return red[0];
}

__global__ __launch_bounds__(HH)
void head_kernel(const float* __restrict__ h2,
                 const float* __restrict__ gamma,
                 const float* __restrict__ beta,
                 const float* __restrict__ hw,
                 const float* __restrict__ hb,
                 float* __restrict__ outp)
{
    __shared__ float red[8];
    const int b = blockIdx.x;
    const int tid = threadIdx.x;

    float v  = h2[(size_t)b * HH + tid];
    float mu = block_sum_256(v, red) * (1.0f / HH);
    float d  = v - mu;
    float var = block_sum_256(d * d, red) * (1.0f / HH);
    float y  = d * rsqrtf(var + 1e-5f) * gamma[tid] + beta[tid];
    float gl = 0.5f * y * (1.0f + erff(y * 0.70710678118654752440f));
    float s  = block_sum_256(gl * hw[tid], red);
    if (tid == 0) outp[b] = s + hb[0];
}

// ---------------- launch ----------------------------------------------------
extern "C" void kernel_launch(void* const* d_in, const int* in_sizes, int n_in,
                              void* d_out, int out_size)
{
    (void)in_sizes; (void)n_in; (void)out_size;

    const float* x     = (const float*)d_in[0];
    const float* w_ih0 = (const float*)d_in[1];
    const float* w_hh0 = (const float*)d_in[2];
    const float* b_ih0 = (const float*)d_in[3];
    const float* b_hh0 = (const float*)d_in[4];
    const float* w_ih1 = (const float*)d_in[5];
    const float* w_hh1 = (const float*)d_in[6];
    const float* b_ih1 = (const float*)d_in[7];
    const float* b_hh1 = (const float*)d_in[8];
    const float* ln_g  = (const float*)d_in[9];
    const float* ln_b  = (const float*)d_in[10];
    const float* hw    = (const float*)d_in[11];
    const float* hb    = (const float*)d_in[12];
    float* outp = (float*)d_out;

    __nv_bfloat16 *xhi, *xlo, *w0hi, *w0lo, *w1hi, *w1lo, *h1hi, *h1lo;
    float *xp, *h2l;
    cudaGetSymbolAddress((void**)&xhi,  g_xhi);
    cudaGetSymbolAddress((void**)&xlo,  g_xlo);
    cudaGetSymbolAddress((void**)&w0hi, g_w0hi);
    cudaGetSymbolAddress((void**)&w0lo, g_w0lo);
    cudaGetSymbolAddress((void**)&w1hi, g_w1hi);
    cudaGetSymbolAddress((void**)&w1lo, g_w1lo);
    cudaGetSymbolAddress((void**)&h1hi, g_h1hi);
    cudaGetSymbolAddress((void**)&h1lo, g_h1lo);
    cudaGetSymbolAddress((void**)&xp,   g_xp);
    cudaGetSymbolAddress((void**)&h2l,  g_h2last);

    cudaFuncSetAttribute(lstm_rec_tc<true>,
                         cudaFuncAttributeMaxDynamicSharedMemorySize, SMEM_REC);
    cudaFuncSetAttribute(lstm_rec_tc<false>,
                         cudaFuncAttributeMaxDynamicSharedMemorySize, SMEM_REC);

    cvt_pair_kernel<<<512, 256>>>(x,     xhi,  xlo,  (size_t)MTOT * IIN);
    cvt_pair_kernel<<<128, 256>>>(w_ih0, w0hi, w0lo, (size_t)4 * HH * IIN);
    cvt_pair_kernel<<<256, 256>>>(w_ih1, w1hi, w1lo, (size_t)4 * HH * HH);

    // layer 0
    gemm_xproj_wmma<IIN><<<dim3(MTOT / 128, 8), 256>>>(xhi, xlo, w0hi, w0lo, xp);
    lstm_rec_tc<true><<<NCLUSTER * CLUSTER, 256, SMEM_REC>>>(
        xp, w_hh0, b_ih0, b_hh0, h1hi, h1lo, nullptr);

    // layer 1
    gemm_xproj_wmma<HH><<<dim3(MTOT / 128, 8), 256>>>(h1hi, h1lo, w1hi, w1lo, xp);
    lstm_rec_tc<false><<<NCLUSTER * CLUSTER, 256, SMEM_REC>>>(
        xp, w_hh1, b_ih1, b_hh1, nullptr, nullptr, h2l);

    head_kernel<<<BATCH, HH>>>(h2l, ln_g, ln_b, hw, hb, outp);
}

// round 7
// speedup vs baseline: 1.2048x; 1.2048x over previous
#include <cuda_runtime.h>
#include <cuda_bf16.h>
#include <cuda_fp16.h>
#include <mma.h>
#include <math.h>
#include <stddef.h>
#include <stdint.h>

using namespace nvcuda;

#define BATCH 512
#define TT    256
#define IIN   64
#define HH    256
#define BB    4
#define NBLK  (BATCH / BB)          // 128 recurrence CTAs
#define MTOT  (BATCH * TT)          // 131072 rows for x_proj GEMMs

// ---------------- static device scratch ------------------------------------
__device__ __nv_bfloat16 g_xhi[(size_t)MTOT * IIN];
__device__ __nv_bfloat16 g_xlo[(size_t)MTOT * IIN];
__device__ __nv_bfloat16 g_w0hi[4 * HH * IIN];
__device__ __nv_bfloat16 g_w0lo[4 * HH * IIN];
__device__ __nv_bfloat16 g_w1hi[4 * HH * HH];
__device__ __nv_bfloat16 g_w1lo[4 * HH * HH];
__device__ __nv_bfloat16 g_h1hi[(size_t)MTOT * HH];
__device__ __nv_bfloat16 g_h1lo[(size_t)MTOT * HH];
__device__ float g_xp[(size_t)4 * MTOT * HH];     // [4][MTOT][256] gate-major
__device__ uint2 g_wph0[HH * HH];                 // fp16 packed w_hh [k][j]
__device__ uint2 g_wph1[HH * HH];
__device__ float g_bias0[4 * HH];
__device__ float g_bias1[4 * HH];
__device__ float g_h2last[BATCH * HH];

// ---------------- packed f32x2 helpers (Blackwell FFMA2) --------------------
#define FMA2(acc, w, x) \
    asm("fma.rn.f32x2 %0, %1, %2, %0;" : "+l"(acc) : "l"(w), "l"(x))
#define ADD2(acc, v) \
    asm("add.rn.f32x2 %0, %0, %1;" : "+l"(acc) : "l"(v))

// ---------------- conversions & packing ------------------------------------
__global__ void cvt_pair_kernel(const float* __restrict__ src,
                                __nv_bfloat16* __restrict__ hi,
                                __nv_bfloat16* __restrict__ lo, size_t n)
{
    for (size_t i = (size_t)blockIdx.x * blockDim.x + threadIdx.x; i < n;
         i += (size_t)gridDim.x * blockDim.x) {
        float v = src[i];
        __nv_bfloat16 h = __float2bfloat16(v);
        hi[i] = h;
        lo[i] = __float2bfloat16(v - __bfloat162float(h));
    }
}

// w_hh [4H,H] fp32 -> wph[k][j] = { half2(wi,wf), half2(wg,wo) }
__global__ void pack_whh_f16(const float* __restrict__ w_hh,
                             const float* __restrict__ b_ih,
                             const float* __restrict__ b_hh,
                             uint2* __restrict__ wp,
                             float* __restrict__ bp)
{
    for (int idx = blockIdx.x * blockDim.x + threadIdx.x; idx < HH * HH;
         idx += gridDim.x * blockDim.x) {
        int j = idx & (HH - 1);
        int k = idx >> 8;
        float wi = w_hh[(size_t)(0 * HH + j) * HH + k];
        float wf = w_hh[(size_t)(1 * HH + j) * HH + k];
        float wg = w_hh[(size_t)(2 * HH + j) * HH + k];
        float wo = w_hh[(size_t)(3 * HH + j) * HH + k];
        __half2 hif = __floats2half2_rn(wi, wf);
        __half2 hgo = __floats2half2_rn(wg, wo);
        uint2 o;
        o.x = *(uint32_t*)&hif;
        o.y = *(uint32_t*)&hgo;
        wp[k * HH + j] = o;
    }
    for (int r = blockIdx.x * blockDim.x + threadIdx.x; r < 4 * HH;
         r += gridDim.x * blockDim.x)
        bp[r] = b_ih[r] + b_hh[r];
}

// ---------------- x_proj GEMM on HMMA (R4-proven: 8 warps, 32x64 tile) -------
// C[M,1024] = A[M,K] @ B[1024,K]^T, fp32 accum. Scattered to xp[4][MTOT][256].
template <int K>
__global__ __launch_bounds__(256, 1)
void gemm_xproj_wmma(const __nv_bfloat16* __restrict__ Ahi,
                     const __nv_bfloat16* __restrict__ Alo,
                     const __nv_bfloat16* __restrict__ Bhi,
                     const __nv_bfloat16* __restrict__ Blo,
                     float* __restrict__ xp)
{
    const int w  = threadIdx.x >> 5;
    const int wm = w & 3, wn = w >> 2;
    const size_t m0 = (size_t)blockIdx.x * 128 + wm * 32;
    const int    n0 = blockIdx.y * 128 + wn * 64;

    wmma::fragment<wmma::accumulator, 16, 16, 16, float> acc[2][4];
#pragma unroll
    for (int i = 0; i < 2; ++i)
#pragma unroll
        for (int f = 0; f < 4; ++f) wmma::fill_fragment(acc[i][f], 0.0f);

#pragma unroll
    for (int term = 0; term < 3; ++term) {
        const __nv_bfloat16* A = (term == 1) ? Alo : Ahi;
        const __nv_bfloat16* B = (term == 2) ? Blo : Bhi;
#pragma unroll
        for (int k0 = 0; k0 < K; k0 += 16) {
            wmma::fragment<wmma::matrix_a, 16, 16, 16, __nv_bfloat16,
                           wmma::row_major> fa[2];
            wmma::load_matrix_sync(fa[0], A + m0 * K + k0, K);
            wmma::load_matrix_sync(fa[1], A + (m0 + 16) * K + k0, K);
#pragma unroll
            for (int f = 0; f < 4; ++f) {
                wmma::fragment<wmma::matrix_b, 16, 16, 16, __nv_bfloat16,
                               wmma::col_major> fb;
                wmma::load_matrix_sync(fb, B + (size_t)(n0 + f * 16) * K + k0, K);
                wmma::mma_sync(acc[0][f], fa[0], fb, acc[0][f]);
                wmma::mma_sync(acc[1][f], fa[1], fb, acc[1][f]);
            }
        }
    }

#pragma unroll
    for (int i = 0; i < 2; ++i)
#pragma unroll
        for (int f = 0; f < 4; ++f) {
            int c0 = n0 + f * 16;
            int g = c0 >> 8, j0 = c0 & 255;
            float* dst = xp + ((size_t)g * MTOT + m0 + i * 16) * HH + j0;
            wmma::store_matrix_sync(dst, acc[i][f], HH, wmma::mem_row_major);
        }
}

// ---------------- recurrence: split-K, packed FFMA2, fp16 weights ------------
// 512 threads: j = tid&255 (hidden index), kh = tid>>8 (K-half).
// Weights fp16 [k][j] as {half2(wi,wf), half2(wg,wo)} (8B per (k,j) -> halved
// L2 traffic), cvt to f32 pairs in-register; gate pairs (i,f),(g,o) accumulate
// as f32x2 via FMA2. h stored duplicated {h,h} in smem (broadcast LDS.64).
// Each K-half finalizes 2 of the 4 batches; xp gate values are prefetched at
// the top of each step so DRAM latency overlaps the FMA2 loop.
template <bool STORE_PAIR>
__global__ __launch_bounds__(512, 1)
void lstm_rec_kernel(const float* __restrict__ xp,   // [4][MTOT][256]
                     const uint2* __restrict__ wph,  // [256][256]
                     const float* __restrict__ bp,   // [4*256]
                     __nv_bfloat16* __restrict__ ohi,
                     __nv_bfloat16* __restrict__ olo,
                     float* __restrict__ olast)      // [BATCH][HH]
{
    __shared__ __align__(16) unsigned long long shd[HH * BB];      // {h,h} dup
    __shared__ __align__(16) unsigned long long spart[BB * 2 * HH];

    const int tid = threadIdx.x;
    const int j   = tid & (HH - 1);
    const int kh  = tid >> 8;                 // 0 or 1
    const int klo = kh * 128, khi = klo + 128;
    const int bfin = kh * 2;                  // batches this half finalizes
    const int bexp = 2 - kh * 2;              // batches whose partials we export
    const int b0   = blockIdx.x * BB;

    const float bi = bp[0 * HH + j], bf_ = bp[1 * HH + j];
    const float bg = bp[2 * HH + j], bo  = bp[3 * HH + j];

    float c[2] = {0.0f, 0.0f};

    for (int i = tid; i < HH * BB; i += 512) shd[i] = 0ull;
    __syncthreads();

    for (int t = 0; t < TT; ++t) {
        // ---- prefetch x_proj gate values for the 2 batches we finalize ----
        float xg[2][4];
#pragma unroll
        for (int bb = 0; bb < 2; ++bb) {
            const size_t m = (size_t)(b0 + bfin + bb) * TT + t;
#pragma unroll
            for (int g = 0; g < 4; ++g)
                xg[bb][g] = __ldg(&xp[((size_t)g * MTOT + m) * HH + j]);
        }

        unsigned long long aif[BB], ago[BB];
#pragma unroll
        for (int b = 0; b < BB; ++b) { aif[b] = 0ull; ago[b] = 0ull; }

#pragma unroll 4
        for (int k = klo; k < khi; ++k) {
            const uint2 wv = __ldg(&wph[k * HH + j]);
            float2 fif = __half22float2(*(const __half2*)&wv.x);
            float2 fgo = __half22float2(*(const __half2*)&wv.y);
            unsigned long long wif = *(unsigned long long*)&fif;
            unsigned long long wgo = *(unsigned long long*)&fgo;
#pragma unroll
            for (int b = 0; b < BB; ++b) {
                unsigned long long xd = shd[k * BB + b];  // broadcast
                FMA2(aif[b], wif, xd);
                FMA2(ago[b], wgo, xd);
            }
        }

        // export partials for the batches the OTHER half finalizes
#pragma unroll
        for (int bb = 0; bb < 2; ++bb) {
            int b = bexp + bb;
            spart[(b * 2 + 0) * HH + j] = aif[b];
            spart[(b * 2 + 1) * HH + j] = ago[b];
        }
        __syncthreads();

#pragma unroll
        for (int bb = 0; bb < 2; ++bb) {
            int b = bfin + bb;
            unsigned long long vif = aif[b], vgo = ago[b];
            ADD2(vif, spart[(b * 2 + 0) * HH + j]);
            ADD2(vgo, spart[(b * 2 + 1) * HH + j]);
            float vi, vf, vg, vo;
            asm("mov.b64 {%0,%1}, %2;" : "=f"(vi), "=f"(vf) : "l"(vif));
            asm("mov.b64 {%0,%1}, %2;" : "=f"(vg), "=f"(vo) : "l"(vgo));
            vi += bi  + xg[bb][0];
            vf += bf_ + xg[bb][1];
            vg += bg  + xg[bb][2];
            vo += bo  + xg[bb][3];
            float iv = 1.0f / (1.0f + expf(-vi));
            float fv = 1.0f / (1.0f + expf(-vf));
            float gv = tanhf(vg);
            float ov = 1.0f / (1.0f + expf(-vo));
            c[bb] = fv * c[bb] + iv * gv;
            float hv = ov * tanhf(c[bb]);
            unsigned long long hd;
            asm("mov.b64 %0, {%1,%1};" : "=l"(hd) : "f"(hv));
            shd[j * BB + b] = hd;
            if (STORE_PAIR) {
                const size_t m = (size_t)(b0 + b) * TT + t;
                __nv_bfloat16 h16 = __float2bfloat16(hv);
                ohi[m * HH + j] = h16;
                olo[m * HH + j] = __float2bfloat16(hv - __bfloat162float(h16));
            } else if (t == TT - 1) {
                olast[(size_t)(b0 + b) * HH + j] = hv;
            }
        }
        __syncthreads();
    }
}

// ---------------- LayerNorm + exact GELU + linear head ----------------------
__device__ __forceinline__ float block_sum_256(float v, float* red)
{
    __syncthreads();
#pragma unroll
    for (int o = 16; o > 0; o >>= 1) v += __shfl_down_sync(0xffffffffu, v, o);
    if ((threadIdx.x & 31) == 0) red[threadIdx.x >> 5] = v;
    __syncthreads();
    if (threadIdx.x < 8) {
        v = red[threadIdx.x];
#pragma unroll
        for (int o = 4; o > 0; o >>= 1) v += __shfl_down_sync(0xffu, v, o);
        if (threadIdx.x == 0) red[0] = v;
    }
    __syncthreads();
    return red[0];
}

__global__ __launch_bounds__(HH)
void head_kernel(const float* __restrict__ h2,
                 const float* __restrict__ gamma,
                 const float* __restrict__ beta,
                 const float* __restrict__ hw,
                 const float* __restrict__ hb,
                 float* __restrict__ outp)
{
    __shared__ float red[8];
    const int b = blockIdx.x;
    const int tid = threadIdx.x;

    float v  = h2[(size_t)b * HH + tid];
    float mu = block_sum_256(v, red) * (1.0f / HH);
    float d  = v - mu;
    float var = block_sum_256(d * d, red) * (1.0f / HH);
    float y  = d * rsqrtf(var + 1e-5f) * gamma[tid] + beta[tid];
    float gl = 0.5f * y * (1.0f + erff(y * 0.70710678118654752440f));
    float s  = block_sum_256(gl * hw[tid], red);
    if (tid == 0) outp[b] = s + hb[0];
}

// ---------------- launch ----------------------------------------------------
extern "C" void kernel_launch(void* const* d_in, const int* in_sizes, int n_in,
                              void* d_out, int out_size)
{
    (void)in_sizes; (void)n_in; (void)out_size;

    const float* x     = (const float*)d_in[0];
    const float* w_ih0 = (const float*)d_in[1];
    const float* w_hh0 = (const float*)d_in[2];
    const float* b_ih0 = (const float*)d_in[3];
    const float* b_hh0 = (const float*)d_in[4];
    const float* w_ih1 = (const float*)d_in[5];
    const float* w_hh1 = (const float*)d_in[6];
    const float* b_ih1 = (const float*)d_in[7];
    const float* b_hh1 = (const float*)d_in[8];
    const float* ln_g  = (const float*)d_in[9];
    const float* ln_b  = (const float*)d_in[10];
    const float* hw    = (const float*)d_in[11];
    const float* hb    = (const float*)d_in[12];
    float* outp = (float*)d_out;

    __nv_bfloat16 *xhi, *xlo, *w0hi, *w0lo, *w1hi, *w1lo, *h1hi, *h1lo;
    uint2 *wph0, *wph1;
    float *xp, *bp0, *bp1, *h2l;
    cudaGetSymbolAddress((void**)&xhi,  g_xhi);
    cudaGetSymbolAddress((void**)&xlo,  g_xlo);
    cudaGetSymbolAddress((void**)&w0hi, g_w0hi);
    cudaGetSymbolAddress((void**)&w0lo, g_w0lo);
    cudaGetSymbolAddress((void**)&w1hi, g_w1hi);
    cudaGetSymbolAddress((void**)&w1lo, g_w1lo);
    cudaGetSymbolAddress((void**)&h1hi, g_h1hi);
    cudaGetSymbolAddress((void**)&h1lo, g_h1lo);
    cudaGetSymbolAddress((void**)&xp,   g_xp);
    cudaGetSymbolAddress((void**)&wph0, g_wph0);
    cudaGetSymbolAddress((void**)&wph1, g_wph1);
    cudaGetSymbolAddress((void**)&bp0,  g_bias0);
    cudaGetSymbolAddress((void**)&bp1,  g_bias1);
    cudaGetSymbolAddress((void**)&h2l,  g_h2last);

    cvt_pair_kernel<<<512, 256>>>(x,     xhi,  xlo,  (size_t)MTOT * IIN);
    cvt_pair_kernel<<<128, 256>>>(w_ih0, w0hi, w0lo, (size_t)4 * HH * IIN);
    cvt_pair_kernel<<<256, 256>>>(w_ih1, w1hi, w1lo, (size_t)4 * HH * HH);
    pack_whh_f16<<<128, 256>>>(w_hh0, b_ih0, b_hh0, wph0, bp0);
    pack_whh_f16<<<128, 256>>>(w_hh1, b_ih1, b_hh1, wph1, bp1);

    // layer 0: x_proj GEMM (K=64) then recurrence (emits h1 as bf16 hi/lo)
    gemm_xproj_wmma<IIN><<<dim3(MTOT / 128, 8), 256>>>(xhi, xlo, w0hi, w0lo, xp);
    lstm_rec_kernel<true><<<NBLK, 512>>>(xp, wph0, bp0, h1hi, h1lo, nullptr);

    // layer 1: x_proj GEMM (K=256) from h1 pair, recurrence keeps last h only
    gemm_xproj_wmma<HH><<<dim3(MTOT / 128, 8), 256>>>(h1hi, h1lo, w1hi, w1lo, xp);
    lstm_rec_kernel<false><<<NBLK, 512>>>(xp, wph1, bp1, nullptr, nullptr, h2l);

    head_kernel<<<BATCH, HH>>>(h2l, ln_g, ln_b, hw, hb, outp);
}

// round 8
// speedup vs baseline: 1.4249x; 1.1827x over previous
#include <cuda_runtime.h>
#include <cuda_bf16.h>
#include <cuda_fp16.h>
#include <mma.h>
#include <math.h>
#include <stddef.h>
#include <stdint.h>

using namespace nvcuda;

#define BATCH 512
#define TT    256
#define IIN   64
#define HH    256
#define BB    4
#define NBLK  (BATCH / BB)          // 128 recurrence CTAs
#define MTOT  (BATCH * TT)          // 131072 rows for x_proj GEMMs

// GEMM staging
#define LDT        72               // padded smem ld (bf16 elems)
#define GEMM_SMEM  (4 * 128 * LDT * 2)      // 73728 B (A/B x hi/lo)

// Recurrence weight cache: KCH k-slices per K-half live in smem
#define KCH        44
#define WSM_U2     (2 * KCH * HH)           // uint2 elements
#define REC_SMEM   (WSM_U2 * 8)             // 180224 B dynamic

// ---------------- static device scratch ------------------------------------
__device__ __nv_bfloat16 g_xhi[(size_t)MTOT * IIN];
__device__ __nv_bfloat16 g_xlo[(size_t)MTOT * IIN];
__device__ __nv_bfloat16 g_w0hi[4 * HH * IIN];
__device__ __nv_bfloat16 g_w0lo[4 * HH * IIN];
__device__ __nv_bfloat16 g_w1hi[4 * HH * HH];
__device__ __nv_bfloat16 g_w1lo[4 * HH * HH];
__device__ __nv_bfloat16 g_h1hi[(size_t)MTOT * HH];
__device__ __nv_bfloat16 g_h1lo[(size_t)MTOT * HH];
__device__ float g_xp[(size_t)4 * MTOT * HH];     // [4][MTOT][256] gate-major
__device__ uint2 g_wph0[HH * HH];                 // fp16 packed w_hh [k][j]
__device__ uint2 g_wph1[HH * HH];
__device__ float g_bias0[4 * HH];
__device__ float g_bias1[4 * HH];
__device__ float g_h2last[BATCH * HH];

// ---------------- packed f32x2 helpers (Blackwell FFMA2) --------------------
#define FMA2(acc, w, x) \
    asm("fma.rn.f32x2 %0, %1, %2, %0;" : "+l"(acc) : "l"(w), "l"(x))
#define ADD2(acc, v) \
    asm("add.rn.f32x2 %0, %0, %1;" : "+l"(acc) : "l"(v))

// ---------------- conversions & packing ------------------------------------
__global__ void cvt_pair_kernel(const float* __restrict__ src,
                                __nv_bfloat16* __restrict__ hi,
                                __nv_bfloat16* __restrict__ lo, size_t n)
{
    for (size_t i = (size_t)blockIdx.x * blockDim.x + threadIdx.x; i < n;
         i += (size_t)gridDim.x * blockDim.x) {
        float v = src[i];
        __nv_bfloat16 h = __float2bfloat16(v);
        hi[i] = h;
        lo[i] = __float2bfloat16(v - __bfloat162float(h));
    }
}

// w_hh [4H,H] fp32 -> wph[k][j] = { half2(wi,wf), half2(wg,wo) }
__global__ void pack_whh_f16(const float* __restrict__ w_hh,
                             const float* __restrict__ b_ih,
                             const float* __restrict__ b_hh,
                             uint2* __restrict__ wp,
                             float* __restrict__ bp)
{
    for (int idx = blockIdx.x * blockDim.x + threadIdx.x; idx < HH * HH;
         idx += gridDim.x * blockDim.x) {
        int j = idx & (HH - 1);
        int k = idx >> 8;
        float wi = w_hh[(size_t)(0 * HH + j) * HH + k];
        float wf = w_hh[(size_t)(1 * HH + j) * HH + k];
        float wg = w_hh[(size_t)(2 * HH + j) * HH + k];
        float wo = w_hh[(size_t)(3 * HH + j) * HH + k];
        __half2 hif = __floats2half2_rn(wi, wf);
        __half2 hgo = __floats2half2_rn(wg, wo);
        uint2 o;
        o.x = *(uint32_t*)&hif;
        o.y = *(uint32_t*)&hgo;
        wp[k * HH + j] = o;
    }
    for (int r = blockIdx.x * blockDim.x + threadIdx.x; r < 4 * HH;
         r += gridDim.x * blockDim.x)
        bp[r] = b_ih[r] + b_hh[r];
}

// ---------------- x_proj GEMM: smem-staged HMMA (bf16 hi/lo 3-term) ----------
// C[M,1024] = A[M,K] @ B[1024,K]^T, fp32 accum, scattered to xp[4][MTOT][256].
// CTA tile 128x128, 8 warps (4x2), warp tile 32x64 (proven reg footprint).
// A/B tiles (hi & lo) staged in smem per 64-wide K chunk, ld=72 to spread banks.
template <int K>
__global__ __launch_bounds__(256, 1)
void gemm_xproj_smem(const __nv_bfloat16* __restrict__ Ahi,
                     const __nv_bfloat16* __restrict__ Alo,
                     const __nv_bfloat16* __restrict__ Bhi,
                     const __nv_bfloat16* __restrict__ Blo,
                     float* __restrict__ xp)
{
    extern __shared__ __align__(16) __nv_bfloat16 sm[];
    __nv_bfloat16* sAhi = sm;
    __nv_bfloat16* sAlo = sm + 128 * LDT;
    __nv_bfloat16* sBhi = sm + 2 * 128 * LDT;
    __nv_bfloat16* sBlo = sm + 3 * 128 * LDT;

    const int tid = threadIdx.x;
    const int w   = tid >> 5;
    const int wm  = w & 3, wn = w >> 2;
    const size_t mBase = (size_t)blockIdx.x * 128;
    const int    nBase = blockIdx.y * 128;

    wmma::fragment<wmma::accumulator, 16, 16, 16, float> acc[2][4];
#pragma unroll
    for (int i = 0; i < 2; ++i)
#pragma unroll
        for (int f = 0; f < 4; ++f) wmma::fill_fragment(acc[i][f], 0.0f);

    for (int kc = 0; kc < K; kc += 64) {
        if (kc) __syncthreads();           // previous chunk's reads done
        for (int i = tid; i < 1024; i += 256) {
            int row = i >> 3;
            int col = (i & 7) * 8;
            size_t ga = (mBase + row) * K + kc + col;
            size_t gb = ((size_t)(nBase + row)) * K + kc + col;
            *(uint4*)(sAhi + row * LDT + col) = *(const uint4*)(Ahi + ga);
            *(uint4*)(sAlo + row * LDT + col) = *(const uint4*)(Alo + ga);
            *(uint4*)(sBhi + row * LDT + col) = *(const uint4*)(Bhi + gb);
            *(uint4*)(sBlo + row * LDT + col) = *(const uint4*)(Blo + gb);
        }
        __syncthreads();

#pragma unroll
        for (int term = 0; term < 3; ++term) {
            const __nv_bfloat16* A = (term == 1) ? sAlo : sAhi;
            const __nv_bfloat16* B = (term == 2) ? sBlo : sBhi;
#pragma unroll
            for (int k0 = 0; k0 < 64; k0 += 16) {
                wmma::fragment<wmma::matrix_a, 16, 16, 16, __nv_bfloat16,
                               wmma::row_major> fa[2];
                wmma::load_matrix_sync(fa[0], A + (wm * 32) * LDT + k0, LDT);
                wmma::load_matrix_sync(fa[1], A + (wm * 32 + 16) * LDT + k0, LDT);
#pragma unroll
                for (int f = 0; f < 4; ++f) {
                    wmma::fragment<wmma::matrix_b, 16, 16, 16, __nv_bfloat16,
                                   wmma::col_major> fb;
                    wmma::load_matrix_sync(fb, B + (wn * 64 + f * 16) * LDT + k0,
                                           LDT);
                    wmma::mma_sync(acc[0][f], fa[0], fb, acc[0][f]);
                    wmma::mma_sync(acc[1][f], fa[1], fb, acc[1][f]);
                }
            }
        }
    }

    const size_t m0 = mBase + wm * 32;
    const int    n0 = nBase + wn * 64;
#pragma unroll
    for (int i = 0; i < 2; ++i)
#pragma unroll
        for (int f = 0; f < 4; ++f) {
            int c0 = n0 + f * 16;
            int g = c0 >> 8, j0 = c0 & 255;
            float* dst = xp + ((size_t)g * MTOT + m0 + i * 16) * HH + j0;
            wmma::store_matrix_sync(dst, acc[i][f], HH, wmma::mem_row_major);
        }
}

// ---------------- recurrence: split-K FFMA2, fp16 weights, smem cache --------
// 512 threads: j = tid&255, kh = tid>>8 (K-half of 128 k each).
// First KCH k of each half are served from a one-time smem cache (29-cyc LDS,
// zero L2 traffic); the rest stream from L2 with unroll-8 MLP batching.
template <bool STORE_PAIR>
__global__ __launch_bounds__(512, 1)
void lstm_rec_kernel(const float* __restrict__ xp,   // [4][MTOT][256]
                     const uint2* __restrict__ wph,  // [256][256]
                     const float* __restrict__ bp,   // [4*256]
                     __nv_bfloat16* __restrict__ ohi,
                     __nv_bfloat16* __restrict__ olo,
                     float* __restrict__ olast)      // [BATCH][HH]
{
    extern __shared__ __align__(16) uint2 wsm[];               // [2][KCH][HH]
    __shared__ __align__(16) unsigned long long shd[HH * BB];  // {h,h} dup
    __shared__ __align__(16) unsigned long long spart[BB * 2 * HH];

    const int tid = threadIdx.x;
    const int j   = tid & (HH - 1);
    const int kh  = tid >> 8;                 // 0 or 1
    const int klo = kh * 128;
    const int bfin = kh * 2;                  // batches this half finalizes
    const int bexp = 2 - kh * 2;              // batches whose partials we export
    const int b0   = blockIdx.x * BB;

    // one-time weight cache fill: wsm[(half*KCH + kidx)*HH + jj]
    for (int i = tid; i < WSM_U2; i += 512) {
        int jj = i & (HH - 1);
        int kk = i >> 8;                      // 0..2*KCH-1
        int half = (kk >= KCH);
        int kidx = kk - half * KCH;
        wsm[i] = wph[(half * 128 + kidx) * HH + jj];
    }

    const float bi = bp[0 * HH + j], bf_ = bp[1 * HH + j];
    const float bg = bp[2 * HH + j], bo  = bp[3 * HH + j];

    float c[2] = {0.0f, 0.0f};

    for (int i = tid; i < HH * BB; i += 512) shd[i] = 0ull;
    __syncthreads();

    for (int t = 0; t < TT; ++t) {
        // prefetch x_proj gate values for the 2 batches we finalize
        float xg[2][4];
#pragma unroll
        for (int bb = 0; bb < 2; ++bb) {
            const size_t m = (size_t)(b0 + bfin + bb) * TT + t;
#pragma unroll
            for (int g = 0; g < 4; ++g)
                xg[bb][g] = __ldg(&xp[((size_t)g * MTOT + m) * HH + j]);
        }

        unsigned long long aif[BB], ago[BB];
#pragma unroll
        for (int b = 0; b < BB; ++b) { aif[b] = 0ull; ago[b] = 0ull; }

        // cached segment: weights from smem
#pragma unroll 4
        for (int kk = 0; kk < KCH; ++kk) {
            const uint2 wv = wsm[(kh * KCH + kk) * HH + j];
            float2 fif = __half22float2(*(const __half2*)&wv.x);
            float2 fgo = __half22float2(*(const __half2*)&wv.y);
            unsigned long long wif = *(unsigned long long*)&fif;
            unsigned long long wgo = *(unsigned long long*)&fgo;
            const int k = klo + kk;
#pragma unroll
            for (int b = 0; b < BB; ++b) {
                unsigned long long xd = shd[k * BB + b];
                FMA2(aif[b], wif, xd);
                FMA2(ago[b], wgo, xd);
            }
        }

        // streamed segment: weights from L2, deep unroll for MLP
#pragma unroll 8
        for (int k = klo + KCH; k < klo + 128; ++k) {
            const uint2 wv = __ldg(&wph[k * HH + j]);
            float2 fif = __half22float2(*(const __half2*)&wv.x);
            float2 fgo = __half22float2(*(const __half2*)&wv.y);
            unsigned long long wif = *(unsigned long long*)&fif;
            unsigned long long wgo = *(unsigned long long*)&fgo;
#pragma unroll
            for (int b = 0; b < BB; ++b) {
                unsigned long long xd = shd[k * BB + b];
                FMA2(aif[b], wif, xd);
                FMA2(ago[b], wgo, xd);
            }
        }

        // export partials for the batches the OTHER half finalizes
#pragma unroll
        for (int bb = 0; bb < 2; ++bb) {
            int b = bexp + bb;
            spart[(b * 2 + 0) * HH + j] = aif[b];
            spart[(b * 2 + 1) * HH + j] = ago[b];
        }
        __syncthreads();

#pragma unroll
        for (int bb = 0; bb < 2; ++bb) {
            int b = bfin + bb;
            unsigned long long vif = aif[b], vgo = ago[b];
            ADD2(vif, spart[(b * 2 + 0) * HH + j]);
            ADD2(vgo, spart[(b * 2 + 1) * HH + j]);
            float vi, vf, vg, vo;
            asm("mov.b64 {%0,%1}, %2;" : "=f"(vi), "=f"(vf) : "l"(vif));
            asm("mov.b64 {%0,%1}, %2;" : "=f"(vg), "=f"(vo) : "l"(vgo));
            vi += bi  + xg[bb][0];
            vf += bf_ + xg[bb][1];
            vg += bg  + xg[bb][2];
            vo += bo  + xg[bb][3];
            float iv = 1.0f / (1.0f + expf(-vi));
            float fv = 1.0f / (1.0f + expf(-vf));
            float gv = tanhf(vg);
            float ov = 1.0f / (1.0f + expf(-vo));
            c[bb] = fv * c[bb] + iv * gv;
            float hv = ov * tanhf(c[bb]);
            unsigned long long hd;
            asm("mov.b64 %0, {%1,%1};" : "=l"(hd) : "f"(hv));
            shd[j * BB + b] = hd;
            if (STORE_PAIR) {
                const size_t m = (size_t)(b0 + b) * TT + t;
                __nv_bfloat16 h16 = __float2bfloat16(hv);
                ohi[m * HH + j] = h16;
                olo[m * HH + j] = __float2bfloat16(hv - __bfloat162float(h16));
            } else if (t == TT - 1) {
                olast[(size_t)(b0 + b) * HH + j] = hv;
            }
        }
        __syncthreads();
    }
}

// ---------------- LayerNorm + exact GELU + linear head ----------------------
__device__ __forceinline__ float block_sum_256(float v, float* red)
{
    __syncthreads();
#pragma unroll
    for (int o = 16; o > 0; o >>= 1) v += __shfl_down_sync(0xffffffffu, v, o);
    if ((threadIdx.x & 31) == 0) red[threadIdx.x >> 5] = v;
    __syncthreads();
    if (threadIdx.x < 8) {
        v = red[threadIdx.x];
#pragma unroll
        for (int o = 4; o > 0; o >>= 1) v += __shfl_down_sync(0xffu, v, o);
        if (threadIdx.x == 0) red[0] = v;
    }
    __syncthreads();
    return red[0];
}

__global__ __launch_bounds__(HH)
void head_kernel(const float* __restrict__ h2,
                 const float* __restrict__ gamma,
                 const float* __restrict__ beta,
                 const float* __restrict__ hw,
                 const float* __restrict__ hb,
                 float* __restrict__ outp)
{
    __shared__ float red[8];
    const int b = blockIdx.x;
    const int tid = threadIdx.x;

    float v  = h2[(size_t)b * HH + tid];
    float mu = block_sum_256(v, red) * (1.0f / HH);
    float d  = v - mu;
    float var = block_sum_256(d * d, red) * (1.0f / HH);
    float y  = d * rsqrtf(var + 1e-5f) * gamma[tid] + beta[tid];
    float gl = 0.5f * y * (1.0f + erff(y * 0.70710678118654752440f));
    float s  = block_sum_256(gl * hw[tid], red);
    if (tid == 0) outp[b] = s + hb[0];
}

// ---------------- launch ----------------------------------------------------
extern "C" void kernel_launch(void* const* d_in, const int* in_sizes, int n_in,
                              void* d_out, int out_size)
{
    (void)in_sizes; (void)n_in; (void)out_size;

    const float* x     = (const float*)d_in[0];
    const float* w_ih0 = (const float*)d_in[1];
    const float* w_hh0 = (const float*)d_in[2];
    const float* b_ih0 = (const float*)d_in[3];
    const float* b_hh0 = (const float*)d_in[4];
    const float* w_ih1 = (const float*)d_in[5];
    const float* w_hh1 = (const float*)d_in[6];
    const float* b_ih1 = (const float*)d_in[7];
    const float* b_hh1 = (const float*)d_in[8];
    const float* ln_g  = (const float*)d_in[9];
    const float* ln_b  = (const float*)d_in[10];
    const float* hw    = (const float*)d_in[11];
    const float* hb    = (const float*)d_in[12];
    float* outp = (float*)d_out;

    __nv_bfloat16 *xhi, *xlo, *w0hi, *w0lo, *w1hi, *w1lo, *h1hi, *h1lo;
    uint2 *wph0, *wph1;
    float *xp, *bp0, *bp1, *h2l;
    cudaGetSymbolAddress((void**)&xhi,  g_xhi);
    cudaGetSymbolAddress((void**)&xlo,  g_xlo);
    cudaGetSymbolAddress((void**)&w0hi, g_w0hi);
    cudaGetSymbolAddress((void**)&w0lo, g_w0lo);
    cudaGetSymbolAddress((void**)&w1hi, g_w1hi);
    cudaGetSymbolAddress((void**)&w1lo, g_w1lo);
    cudaGetSymbolAddress((void**)&h1hi, g_h1hi);
    cudaGetSymbolAddress((void**)&h1lo, g_h1lo);
    cudaGetSymbolAddress((void**)&xp,   g_xp);
    cudaGetSymbolAddress((void**)&wph0, g_wph0);
    cudaGetSymbolAddress((void**)&wph1, g_wph1);
    cudaGetSymbolAddress((void**)&bp0,  g_bias0);
    cudaGetSymbolAddress((void**)&bp1,  g_bias1);
    cudaGetSymbolAddress((void**)&h2l,  g_h2last);

    cudaFuncSetAttribute(gemm_xproj_smem<IIN>,
                         cudaFuncAttributeMaxDynamicSharedMemorySize, GEMM_SMEM);
    cudaFuncSetAttribute(gemm_xproj_smem<HH>,
                         cudaFuncAttributeMaxDynamicSharedMemorySize, GEMM_SMEM);
    cudaFuncSetAttribute(lstm_rec_kernel<true>,
                         cudaFuncAttributeMaxDynamicSharedMemorySize, REC_SMEM);
    cudaFuncSetAttribute(lstm_rec_kernel<false>,
                         cudaFuncAttributeMaxDynamicSharedMemorySize, REC_SMEM);

    cvt_pair_kernel<<<512, 256>>>(x,     xhi,  xlo,  (size_t)MTOT * IIN);
    cvt_pair_kernel<<<128, 256>>>(w_ih0, w0hi, w0lo, (size_t)4 * HH * IIN);
    cvt_pair_kernel<<<256, 256>>>(w_ih1, w1hi, w1lo, (size_t)4 * HH * HH);
    pack_whh_f16<<<128, 256>>>(w_hh0, b_ih0, b_hh0, wph0, bp0);
    pack_whh_f16<<<128, 256>>>(w_hh1, b_ih1, b_hh1, wph1, bp1);

    // layer 0: x_proj GEMM (K=64) then recurrence (emits h1 as bf16 hi/lo)
    gemm_xproj_smem<IIN><<<dim3(MTOT / 128, 8), 256, GEMM_SMEM>>>(
        xhi, xlo, w0hi, w0lo, xp);
    lstm_rec_kernel<true><<<NBLK, 512, REC_SMEM>>>(xp, wph0, bp0,
                                                   h1hi, h1lo, nullptr);

    // layer 1: x_proj GEMM (K=256) from h1 pair, recurrence keeps last h only
    gemm_xproj_smem<HH><<<dim3(MTOT / 128, 8), 256, GEMM_SMEM>>>(
        h1hi, h1lo, w1hi, w1lo, xp);
    lstm_rec_kernel<false><<<NBLK, 512, REC_SMEM>>>(xp, wph1, bp1,
                                                    nullptr, nullptr, h2l);

    head_kernel<<<BATCH, HH>>>(h2l, ln_g, ln_b, hw, hb, outp);
}

// round 9
// speedup vs baseline: 1.4503x; 1.0178x over previous
#include <cuda_runtime.h>
#include <cuda_bf16.h>
#include <cuda_fp16.h>
#include <mma.h>
#include <math.h>
#include <stddef.h>
#include <stdint.h>

using namespace nvcuda;
typedef unsigned long long ull;

#define BATCH 512
#define TT    256
#define IIN   64
#define HH    256
#define BB    4
#define NBLK  (BATCH / BB)          // 128 recurrence CTAs
#define MTOT  (BATCH * TT)          // 131072 rows for x_proj GEMMs

// GEMM staging
#define LDT        72               // padded smem ld (bf16 elems)
#define GEMM_SMEM  (4 * 128 * LDT * 2)      // 73728 B

// Recurrence: 4 K-quarters of 64 k; first KCH4 of each quarter cached in smem
#define KCH4       16
#define WSM_U2     (4 * KCH4 * HH)          // uint2 elems  (131072 B)
#define SPART_V2   (32 * 128)               // ulonglong2   (65536 B)
#define REC_DYN    (WSM_U2 * 8 + SPART_V2 * 16)   // 196608 B

// ---------------- static device scratch ------------------------------------
__device__ __nv_bfloat16 g_xhi[(size_t)MTOT * IIN];
__device__ __nv_bfloat16 g_xlo[(size_t)MTOT * IIN];
__device__ __nv_bfloat16 g_w0hi[4 * HH * IIN];
__device__ __nv_bfloat16 g_w0lo[4 * HH * IIN];
__device__ __nv_bfloat16 g_w1hi[4 * HH * HH];
__device__ __nv_bfloat16 g_w1lo[4 * HH * HH];
__device__ __nv_bfloat16 g_h1hi[(size_t)MTOT * HH];
__device__ __nv_bfloat16 g_h1lo[(size_t)MTOT * HH];
__device__ float g_xp[(size_t)4 * MTOT * HH];     // [4][MTOT][256] gate-major
__device__ uint2 g_wph0[HH * HH];                 // fp16 packed w_hh [k][j]
__device__ uint2 g_wph1[HH * HH];
__device__ float g_bias0[4 * HH];
__device__ float g_bias1[4 * HH];
__device__ float g_h2last[BATCH * HH];

// ---------------- packed f32x2 helpers (Blackwell FFMA2) --------------------
#define FMA2(acc, w, x) \
    asm("fma.rn.f32x2 %0, %1, %2, %0;" : "+l"(acc) : "l"(w), "l"(x))
#define ADD2(acc, v) \
    asm("add.rn.f32x2 %0, %0, %1;" : "+l"(acc) : "l"(v))

__device__ __forceinline__ float sig_fast(float x) {
    return __fdividef(1.0f, 1.0f + __expf(-x));
}
__device__ __forceinline__ float tanh_fast(float x) {
    return __fdividef(2.0f, 1.0f + __expf(-2.0f * x)) - 1.0f;
}

// ---------------- conversions & packing ------------------------------------
__global__ void cvt_pair_kernel(const float* __restrict__ src,
                                __nv_bfloat16* __restrict__ hi,
                                __nv_bfloat16* __restrict__ lo, size_t n)
{
    for (size_t i = (size_t)blockIdx.x * blockDim.x + threadIdx.x; i < n;
         i += (size_t)gridDim.x * blockDim.x) {
        float v = src[i];
        __nv_bfloat16 h = __float2bfloat16(v);
        hi[i] = h;
        lo[i] = __float2bfloat16(v - __bfloat162float(h));
    }
}

// w_hh [4H,H] fp32 -> wph[k][j] = { half2(wi,wf), half2(wg,wo) }
__global__ void pack_whh_f16(const float* __restrict__ w_hh,
                             const float* __restrict__ b_ih,
                             const float* __restrict__ b_hh,
                             uint2* __restrict__ wp,
                             float* __restrict__ bp)
{
    for (int idx = blockIdx.x * blockDim.x + threadIdx.x; idx < HH * HH;
         idx += gridDim.x * blockDim.x) {
        int j = idx & (HH - 1);
        int k = idx >> 8;
        float wi = w_hh[(size_t)(0 * HH + j) * HH + k];
        float wf = w_hh[(size_t)(1 * HH + j) * HH + k];
        float wg = w_hh[(size_t)(2 * HH + j) * HH + k];
        float wo = w_hh[(size_t)(3 * HH + j) * HH + k];
        __half2 hif = __floats2half2_rn(wi, wf);
        __half2 hgo = __floats2half2_rn(wg, wo);
        uint2 o;
        o.x = *(uint32_t*)&hif;
        o.y = *(uint32_t*)&hgo;
        wp[k * HH + j] = o;
    }
    for (int r = blockIdx.x * blockDim.x + threadIdx.x; r < 4 * HH;
         r += gridDim.x * blockDim.x)
        bp[r] = b_ih[r] + b_hh[r];
}

// ---------------- x_proj GEMM: smem-staged HMMA (bf16 hi/lo 3-term) ----------
template <int K>
__global__ __launch_bounds__(256, 1)
void gemm_xproj_smem(const __nv_bfloat16* __restrict__ Ahi,
                     const __nv_bfloat16* __restrict__ Alo,
                     const __nv_bfloat16* __restrict__ Bhi,
                     const __nv_bfloat16* __restrict__ Blo,
                     float* __restrict__ xp)
{
    extern __shared__ __align__(16) __nv_bfloat16 sm[];
    __nv_bfloat16* sAhi = sm;
    __nv_bfloat16* sAlo = sm + 128 * LDT;
    __nv_bfloat16* sBhi = sm + 2 * 128 * LDT;
    __nv_bfloat16* sBlo = sm + 3 * 128 * LDT;

    const int tid = threadIdx.x;
    const int w   = tid >> 5;
    const int wm  = w & 3, wn = w >> 2;
    const size_t mBase = (size_t)blockIdx.x * 128;
    const int    nBase = blockIdx.y * 128;

    wmma::fragment<wmma::accumulator, 16, 16, 16, float> acc[2][4];
#pragma unroll
    for (int i = 0; i < 2; ++i)
#pragma unroll
        for (int f = 0; f < 4; ++f) wmma::fill_fragment(acc[i][f], 0.0f);

    for (int kc = 0; kc < K; kc += 64) {
        if (kc) __syncthreads();
        for (int i = tid; i < 1024; i += 256) {
            int row = i >> 3;
            int col = (i & 7) * 8;
            size_t ga = (mBase + row) * K + kc + col;
            size_t gb = ((size_t)(nBase + row)) * K + kc + col;
            *(uint4*)(sAhi + row * LDT + col) = *(const uint4*)(Ahi + ga);
            *(uint4*)(sAlo + row * LDT + col) = *(const uint4*)(Alo + ga);
            *(uint4*)(sBhi + row * LDT + col) = *(const uint4*)(Bhi + gb);
            *(uint4*)(sBlo + row * LDT + col) = *(const uint4*)(Blo + gb);
        }
        __syncthreads();

#pragma unroll
        for (int term = 0; term < 3; ++term) {
            const __nv_bfloat16* A = (term == 1) ? sAlo : sAhi;
            const __nv_bfloat16* B = (term == 2) ? sBlo : sBhi;
#pragma unroll
            for (int k0 = 0; k0 < 64; k0 += 16) {
                wmma::fragment<wmma::matrix_a, 16, 16, 16, __nv_bfloat16,
                               wmma::row_major> fa[2];
                wmma::load_matrix_sync(fa[0], A + (wm * 32) * LDT + k0, LDT);
                wmma::load_matrix_sync(fa[1], A + (wm * 32 + 16) * LDT + k0, LDT);
#pragma unroll
                for (int f = 0; f < 4; ++f) {
                    wmma::fragment<wmma::matrix_b, 16, 16, 16, __nv_bfloat16,
                                   wmma::col_major> fb;
                    wmma::load_matrix_sync(fb, B + (wn * 64 + f * 16) * LDT + k0,
                                           LDT);
                    wmma::mma_sync(acc[0][f], fa[0], fb, acc[0][f]);
                    wmma::mma_sync(acc[1][f], fa[1], fb, acc[1][f]);
                }
            }
        }
    }

    const size_t m0 = mBase + wm * 32;
    const int    n0 = nBase + wn * 64;
#pragma unroll
    for (int i = 0; i < 2; ++i)
#pragma unroll
        for (int f = 0; f < 4; ++f) {
            int c0 = n0 + f * 16;
            int g = c0 >> 8, j0 = c0 & 255;
            float* dst = xp + ((size_t)g * MTOT + m0 + i * 16) * HH + j0;
            wmma::store_matrix_sync(dst, acc[i][f], HH, wmma::mem_row_major);
        }
}

// ---------------- recurrence: 2j x K/4 threads, packed FFMA2, fp16 weights ---
// 512 threads = 128 j-pairs x 4 K-quarters (64 k each). Per k-iter a thread
// serves TWO j's with one LDG.128 (weights) and 4 batches with two LDS.128
// (packed {h,h} duplicates) -> 14.5 inst per j (vs 19 before). Quarter q
// finalizes batch q for its two j's; partials exchanged through one 64 KB
// smem round per step. First KCH4 k of each quarter come from a smem cache.
#define DOT_K(WV)                                                              \
    do {                                                                       \
        float2 f0 = __half22float2(*(const __half2*)&(WV).x);                  \
        float2 g0 = __half22float2(*(const __half2*)&(WV).y);                  \
        float2 f1 = __half22float2(*(const __half2*)&(WV).z);                  \
        float2 g1 = __half22float2(*(const __half2*)&(WV).w);                  \
        ull wif0 = *(ull*)&f0, wgo0 = *(ull*)&g0;                              \
        ull wif1 = *(ull*)&f1, wgo1 = *(ull*)&g1;                              \
        ulonglong2 h01 = *(const ulonglong2*)&shd[k * 4];                      \
        ulonglong2 h23 = *(const ulonglong2*)&shd[k * 4 + 2];                  \
        FMA2(aif0[0], wif0, h01.x); FMA2(aif0[1], wif0, h01.y);                \
        FMA2(aif0[2], wif0, h23.x); FMA2(aif0[3], wif0, h23.y);                \
        FMA2(ago0[0], wgo0, h01.x); FMA2(ago0[1], wgo0, h01.y);                \
        FMA2(ago0[2], wgo0, h23.x); FMA2(ago0[3], wgo0, h23.y);                \
        FMA2(aif1[0], wif1, h01.x); FMA2(aif1[1], wif1, h01.y);                \
        FMA2(aif1[2], wif1, h23.x); FMA2(aif1[3], wif1, h23.y);                \
        FMA2(ago1[0], wgo1, h01.x); FMA2(ago1[1], wgo1, h01.y);                \
        FMA2(ago1[2], wgo1, h23.x); FMA2(ago1[3], wgo1, h23.y);                \
    } while (0)

template <bool STORE_PAIR>
__global__ __launch_bounds__(512, 1)
void lstm_rec_kernel(const float* __restrict__ xp,   // [4][MTOT][256]
                     const uint2* __restrict__ wph,  // [256][256]
                     const float* __restrict__ bp,   // [4*256]
                     __nv_bfloat16* __restrict__ ohi,
                     __nv_bfloat16* __restrict__ olo,
                     float* __restrict__ olast)      // [BATCH][HH]
{
    extern __shared__ __align__(16) char dsm[];
    uint2*      wsm   = (uint2*)dsm;                     // [4*KCH4][256]
    ulonglong2* spart = (ulonglong2*)(dsm + WSM_U2 * 8); // [32][128]
    __shared__ __align__(16) ull shd[HH * BB];           // [k][b] {h,h} dup

    const int tid = threadIdx.x;
    const int jp  = tid & 127;
    const int q   = tid >> 7;                 // K-quarter, also finalized batch
    const int j0  = jp * 2;
    const int b0  = blockIdx.x * BB;
    const int bq  = b0 + q;
    const int kbase = q * 64;

    // one-time weight cache fill (first KCH4 k of each quarter)
    for (int i = tid; i < 4 * KCH4 * HH; i += 512) {
        int j  = i & 255;
        int kk = i >> 8;                      // 0 .. 4*KCH4-1
        int qq = kk >> 4, kin = kk & 15;      // KCH4 == 16
        wsm[i] = wph[(qq * 64 + kin) * HH + j];
    }

    float bias[2][4];
#pragma unroll
    for (int jj = 0; jj < 2; ++jj)
#pragma unroll
        for (int g = 0; g < 4; ++g)
            bias[jj][g] = bp[g * HH + j0 + jj];

    float c2[2] = {0.0f, 0.0f};

    for (int i = tid; i < HH * BB; i += 512) shd[i] = 0ull;
    __syncthreads();

    for (int t = 0; t < TT; ++t) {
        // prefetch x_proj pre-activations for (batch q, j0, j0+1)
        const size_t m = (size_t)bq * TT + t;
        float xg[2][4];
#pragma unroll
        for (int g = 0; g < 4; ++g) {
            float2 v = *(const float2*)&xp[((size_t)g * MTOT + m) * HH + j0];
            xg[0][g] = v.x;
            xg[1][g] = v.y;
        }

        ull aif0[4], ago0[4], aif1[4], ago1[4];
#pragma unroll
        for (int b = 0; b < 4; ++b) {
            aif0[b] = 0ull; ago0[b] = 0ull; aif1[b] = 0ull; ago1[b] = 0ull;
        }

        // cached segment (smem weights)
#pragma unroll 4
        for (int kk = 0; kk < KCH4; ++kk) {
            const int k = kbase + kk;
            uint4 wv = *(const uint4*)&wsm[(q * KCH4 + kk) * HH + j0];
            DOT_K(wv);
        }
        // streamed segment (L2 weights), deep unroll for MLP
#pragma unroll 8
        for (int kk = KCH4; kk < 64; ++kk) {
            const int k = kbase + kk;
            uint4 wv = __ldg((const uint4*)&wph[k * HH + j0]);
            DOT_K(wv);
        }

        // export partials for the 3 batches other quarters finalize
#pragma unroll
        for (int b = 0; b < 4; ++b) {
            if (b != q) {
                spart[((q * 4 + b) * 2 + 0) * 128 + jp] =
                    make_ulonglong2(aif0[b], aif1[b]);
                spart[((q * 4 + b) * 2 + 1) * 128 + jp] =
                    make_ulonglong2(ago0[b], ago1[b]);
            }
        }
        __syncthreads();

        // finalize batch q for j0, j0+1
        ull vif[2] = {aif0[q], aif1[q]};
        ull vgo[2] = {ago0[q], ago1[q]};
#pragma unroll
        for (int qq = 0; qq < 4; ++qq) {
            if (qq != q) {
                ulonglong2 p0 = spart[((qq * 4 + q) * 2 + 0) * 128 + jp];
                ulonglong2 p1 = spart[((qq * 4 + q) * 2 + 1) * 128 + jp];
                ADD2(vif[0], p0.x); ADD2(vif[1], p0.y);
                ADD2(vgo[0], p1.x); ADD2(vgo[1], p1.y);
            }
        }

        float hv[2];
#pragma unroll
        for (int jj = 0; jj < 2; ++jj) {
            float vi, vf, vg, vo;
            asm("mov.b64 {%0,%1}, %2;" : "=f"(vi), "=f"(vf) : "l"(vif[jj]));
            asm("mov.b64 {%0,%1}, %2;" : "=f"(vg), "=f"(vo) : "l"(vgo[jj]));
            vi += bias[jj][0] + xg[jj][0];
            vf += bias[jj][1] + xg[jj][1];
            vg += bias[jj][2] + xg[jj][2];
            vo += bias[jj][3] + xg[jj][3];
            float iv = sig_fast(vi);
            float fv = sig_fast(vf);
            float gv = tanh_fast(vg);
            float ov = sig_fast(vo);
            c2[jj] = fv * c2[jj] + iv * gv;
            hv[jj] = ov * tanh_fast(c2[jj]);
            ull hd;
            asm("mov.b64 %0, {%1,%1};" : "=l"(hd) : "f"(hv[jj]));
            shd[(j0 + jj) * 4 + q] = hd;
        }

        if (STORE_PAIR) {
            __nv_bfloat162 h2 = __float22bfloat162_rn(make_float2(hv[0], hv[1]));
            float l0 = hv[0] - __bfloat162float(__low2bfloat16(h2));
            float l1 = hv[1] - __bfloat162float(__high2bfloat16(h2));
            __nv_bfloat162 l2 = __float22bfloat162_rn(make_float2(l0, l1));
            *(uint32_t*)&ohi[m * HH + j0] = *(uint32_t*)&h2;
            *(uint32_t*)&olo[m * HH + j0] = *(uint32_t*)&l2;
        } else if (t == TT - 1) {
            *(float2*)&olast[(size_t)bq * HH + j0] = make_float2(hv[0], hv[1]);
        }
        __syncthreads();
    }
}

// ---------------- LayerNorm + exact GELU + linear head ----------------------
__device__ __forceinline__ float block_sum_256(float v, float* red)
{
    __syncthreads();
#pragma unroll
    for (int o = 16; o > 0; o >>= 1) v += __shfl_down_sync(0xffffffffu, v, o);
    if ((threadIdx.x & 31) == 0) red[threadIdx.x >> 5] = v;
    __syncthreads();
    if (threadIdx.x < 8) {
        v = red[threadIdx.x];
#pragma unroll
        for (int o = 4; o > 0; o >>= 1) v += __shfl_down_sync(0xffu, v, o);
        if (threadIdx.x == 0) red[0] = v;
    }
    __syncthreads();
    return red[0];
}

__global__ __launch_bounds__(HH)
void head_kernel(const float* __restrict__ h2,
                 const float* __restrict__ gamma,
                 const float* __restrict__ beta,
                 const float* __restrict__ hw,
                 const float* __restrict__ hb,
                 float* __restrict__ outp)
{
    __shared__ float red[8];
    const int b = blockIdx.x;
    const int tid = threadIdx.x;

    float v  = h2[(size_t)b * HH + tid];
    float mu = block_sum_256(v, red) * (1.0f / HH);
    float d  = v - mu;
    float var = block_sum_256(d * d, red) * (1.0f / HH);
    float y  = d * rsqrtf(var + 1e-5f) * gamma[tid] + beta[tid];
    float gl = 0.5f * y * (1.0f + erff(y * 0.70710678118654752440f));
    float s  = block_sum_256(gl * hw[tid], red);
    if (tid == 0) outp[b] = s + hb[0];
}

// ---------------- launch ----------------------------------------------------
extern "C" void kernel_launch(void* const* d_in, const int* in_sizes, int n_in,
                              void* d_out, int out_size)
{
    (void)in_sizes; (void)n_in; (void)out_size;

    const float* x     = (const float*)d_in[0];
    const float* w_ih0 = (const float*)d_in[1];
    const float* w_hh0 = (const float*)d_in[2];
    const float* b_ih0 = (const float*)d_in[3];
    const float* b_hh0 = (const float*)d_in[4];
    const float* w_ih1 = (const float*)d_in[5];
    const float* w_hh1 = (const float*)d_in[6];
    const float* b_ih1 = (const float*)d_in[7];
    const float* b_hh1 = (const float*)d_in[8];
    const float* ln_g  = (const float*)d_in[9];
    const float* ln_b  = (const float*)d_in[10];
    const float* hw    = (const float*)d_in[11];
    const float* hb    = (const float*)d_in[12];
    float* outp = (float*)d_out;

    __nv_bfloat16 *xhi, *xlo, *w0hi, *w0lo, *w1hi, *w1lo, *h1hi, *h1lo;
    uint2 *wph0, *wph1;
    float *xp, *bp0, *bp1, *h2l;
    cudaGetSymbolAddress((void**)&xhi,  g_xhi);
    cudaGetSymbolAddress((void**)&xlo,  g_xlo);
    cudaGetSymbolAddress((void**)&w0hi, g_w0hi);
    cudaGetSymbolAddress((void**)&w0lo, g_w0lo);
    cudaGetSymbolAddress((void**)&w1hi, g_w1hi);
    cudaGetSymbolAddress((void**)&w1lo, g_w1lo);
    cudaGetSymbolAddress((void**)&h1hi, g_h1hi);
    cudaGetSymbolAddress((void**)&h1lo, g_h1lo);
    cudaGetSymbolAddress((void**)&xp,   g_xp);
    cudaGetSymbolAddress((void**)&wph0, g_wph0);
    cudaGetSymbolAddress((void**)&wph1, g_wph1);
    cudaGetSymbolAddress((void**)&bp0,  g_bias0);
    cudaGetSymbolAddress((void**)&bp1,  g_bias1);
    cudaGetSymbolAddress((void**)&h2l,  g_h2last);

    cudaFuncSetAttribute(gemm_xproj_smem<IIN>,
                         cudaFuncAttributeMaxDynamicSharedMemorySize, GEMM_SMEM);
    cudaFuncSetAttribute(gemm_xproj_smem<HH>,
                         cudaFuncAttributeMaxDynamicSharedMemorySize, GEMM_SMEM);
    cudaFuncSetAttribute(lstm_rec_kernel<true>,
                         cudaFuncAttributeMaxDynamicSharedMemorySize, REC_DYN);
    cudaFuncSetAttribute(lstm_rec_kernel<false>,
                         cudaFuncAttributeMaxDynamicSharedMemorySize, REC_DYN);

    cvt_pair_kernel<<<512, 256>>>(x,     xhi,  xlo,  (size_t)MTOT * IIN);
    cvt_pair_kernel<<<128, 256>>>(w_ih0, w0hi, w0lo, (size_t)4 * HH * IIN);
    cvt_pair_kernel<<<256, 256>>>(w_ih1, w1hi, w1lo, (size_t)4 * HH * HH);
    pack_whh_f16<<<128, 256>>>(w_hh0, b_ih0, b_hh0, wph0, bp0);
    pack_whh_f16<<<128, 256>>>(w_hh1, b_ih1, b_hh1, wph1, bp1);

    // layer 0: x_proj GEMM (K=64) then recurrence (emits h1 as bf16 hi/lo)
    gemm_xproj_smem<IIN><<<dim3(MTOT / 128, 8), 256, GEMM_SMEM>>>(
        xhi, xlo, w0hi, w0lo, xp);
    lstm_rec_kernel<true><<<NBLK, 512, REC_DYN>>>(xp, wph0, bp0,
                                                  h1hi, h1lo, nullptr);

    // layer 1: x_proj GEMM (K=256) from h1 pair, recurrence keeps last h only
    gemm_xproj_smem<HH><<<dim3(MTOT / 128, 8), 256, GEMM_SMEM>>>(
        h1hi, h1lo, w1hi, w1lo, xp);
    lstm_rec_kernel<false><<<NBLK, 512, REC_DYN>>>(xp, wph1, bp1,
                                                   nullptr, nullptr, h2l);

    head_kernel<<<BATCH, HH>>>(h2l, ln_g, ln_b, hw, hb, outp);
}